// round 1
// baseline (speedup 1.0000x reference)
#include <cuda_runtime.h>
#include <cstdint>

#define NH  12
#define NB  4
#define NT  64
#define NL  128
#define ND  768
#define DH  64
#define NBT 256   // NB*NT

// -------- device scratch (static, allowed) --------
__device__ float g_k[NBT * ND];
__device__ float g_v[NBT * ND];
__device__ float g_M[(size_t)NBT * NH * DH * DH];   // [bt][h][d][e], ~50 MB

// -------- helpers --------
__device__ __forceinline__ uint32_t f2tf(float x) {
    uint32_t r;
    asm("cvt.rna.tf32.f32 %0, %1;" : "=r"(r) : "f"(x));
    return r;
}

__device__ __forceinline__ void mma_tf32(float c[4],
                                         uint32_t a0, uint32_t a1, uint32_t a2, uint32_t a3,
                                         uint32_t b0, uint32_t b1) {
    asm volatile(
        "mma.sync.aligned.m16n8k8.row.col.f32.tf32.tf32.f32 "
        "{%0,%1,%2,%3}, {%4,%5,%6,%7}, {%8,%9}, {%0,%1,%2,%3};"
        : "+f"(c[0]), "+f"(c[1]), "+f"(c[2]), "+f"(c[3])
        : "r"(a0), "r"(a1), "r"(a2), "r"(a3), "r"(b0), "r"(b1));
}

// ============================================================
// Kernel 1: k = edu @ Wk^T, v = edu @ Wv^T   (fp32, small)
// grid (12 n-tiles, 4 m-tiles, 2 {k,v}), 256 threads, 64x64 tile
// ============================================================
__global__ void __launch_bounds__(256) kv_kernel(const float* __restrict__ edu,
                                                 const float* __restrict__ Wk,
                                                 const float* __restrict__ Wv) {
    const float* W = blockIdx.z ? Wv : Wk;
    float* go      = blockIdx.z ? g_v : g_k;

    __shared__ float As[16][68];   // [k][m]
    __shared__ float Bs[16][68];   // [k][n]

    const int tid = threadIdx.x;
    const int tx = tid & 15;       // n dir
    const int ty = tid >> 4;       // m dir
    const int m0 = blockIdx.y * 64;
    const int n0 = blockIdx.x * 64;

    float acc[4][4];
#pragma unroll
    for (int i = 0; i < 4; i++)
#pragma unroll
        for (int j = 0; j < 4; j++) acc[i][j] = 0.f;

    const int lk = tid & 15;       // k for loading
    const int lr = tid >> 4;       // row base for loading

    for (int kt = 0; kt < ND / 16; kt++) {
        const int k0 = kt * 16;
#pragma unroll
        for (int p = 0; p < 4; p++) {
            const int r = lr + p * 16;
            As[lk][r] = edu[(size_t)(m0 + r) * ND + k0 + lk];
            Bs[lk][r] = W[(size_t)(n0 + r) * ND + k0 + lk];
        }
        __syncthreads();
#pragma unroll
        for (int k = 0; k < 16; k++) {
            float a[4], b[4];
#pragma unroll
            for (int i = 0; i < 4; i++) a[i] = As[k][ty * 4 + i];
#pragma unroll
            for (int j = 0; j < 4; j++) b[j] = Bs[k][tx * 4 + j];
#pragma unroll
            for (int i = 0; i < 4; i++)
#pragma unroll
                for (int j = 0; j < 4; j++) acc[i][j] += a[i] * b[j];
        }
        __syncthreads();
    }
#pragma unroll
    for (int i = 0; i < 4; i++)
#pragma unroll
        for (int j = 0; j < 4; j++)
            go[(size_t)(m0 + ty * 4 + i) * ND + n0 + tx * 4 + j] = acc[i][j];
}

// ============================================================
// Kernel 2: speaker-segmented inclusive prefix of k (x) v
// grid (8 speakers, 12 heads, 4 batches), 256 threads
// Each thread owns 16 consecutive elements of the 64x64 matrix.
// ============================================================
__global__ void __launch_bounds__(256) m_kernel(const int* __restrict__ spk) {
    const int s = blockIdx.x, h = blockIdx.y, b = blockIdx.z;
    const int tid = threadIdx.x;

    __shared__ int   sps[NT];
    __shared__ float kk[DH];
    __shared__ float vv[DH];

    if (tid < NT) sps[tid] = spk[b * NT + tid];
    __syncthreads();

    float acc[16];
#pragma unroll
    for (int r = 0; r < 16; r++) acc[r] = 0.f;

    const int dd = tid >> 2;            // d row
    const int e0 = (tid & 3) * 16;      // e base

    for (int t = 0; t < NT; t++) {
        if (sps[t] != s) continue;      // uniform across block
        const int bt = b * NT + t;
        if (tid < DH)            kk[tid] = g_k[(size_t)bt * ND + h * DH + tid];
        else if (tid < 2 * DH)   vv[tid - DH] = g_v[(size_t)bt * ND + h * DH + (tid - DH)];
        __syncthreads();

        const float kd = kk[dd];
#pragma unroll
        for (int r = 0; r < 16; r++) acc[r] += kd * vv[e0 + r];

        float4* dst = reinterpret_cast<float4*>(
            &g_M[((size_t)bt * NH + h) * (DH * DH) + tid * 16]);
        dst[0] = make_float4(acc[0], acc[1], acc[2], acc[3]);
        dst[1] = make_float4(acc[4], acc[5], acc[6], acc[7]);
        dst[2] = make_float4(acc[8], acc[9], acc[10], acc[11]);
        dst[3] = make_float4(acc[12], acc[13], acc[14], acc[15]);
        __syncthreads();
    }
}

// ============================================================
// Kernel 3: fused  out = x + (x @ Wq^T) per-head@ M
// grid (6 n-tiles, 256 bt), 256 threads = 8 warps (2x4 M-by-N)
// Stage 1: 128x128 q-tile via tf32 mma (K=768)
// Stage 2: per-head (128x64)@(64x64) via tf32 mma, + residual
// ============================================================
#define QS_STRIDE 132
#define AB_STRIDE 36
#define MS_STRIDE 72
#define SMEM_UINTS (NL * QS_STRIDE + 2 * NL * AB_STRIDE)   // 26112 -> 104448 B

__global__ void __launch_bounds__(256) main_kernel(const float* __restrict__ x,
                                                   const float* __restrict__ Wq,
                                                   float* __restrict__ out) {
    extern __shared__ uint32_t sm[];
    uint32_t* qs = sm;                        // 128 x 132 (tf32 bits)
    uint32_t* As = sm + NL * QS_STRIDE;       // 128 x 36
    uint32_t* Bs = As + NL * AB_STRIDE;       // 128 x 36
    uint32_t* Ms = As;                        // overlay: 2 x 64 x 72

    const int ntile = blockIdx.x;
    const int bt    = blockIdx.y;
    const int tid   = threadIdx.x;
    const int lane  = tid & 31;
    const int wid   = tid >> 5;
    const int wm    = wid >> 2;   // 0..1 : row half
    const int wn    = wid & 3;    // 0..3 : 32-col slab

    const float* xr = x  + (size_t)bt * NL * ND;
    const float* Wr = Wq + (size_t)ntile * 128 * ND;

    float acc[4][4][4];
#pragma unroll
    for (int i = 0; i < 4; i++)
#pragma unroll
        for (int j = 0; j < 4; j++)
#pragma unroll
            for (int r = 0; r < 4; r++) acc[i][j][r] = 0.f;

    // ---------------- stage 1: q tile ----------------
    for (int kt = 0; kt < ND / 32; kt++) {
        const int k0 = kt * 32;
#pragma unroll
        for (int i = 0; i < 4; i++) {
            const int t  = tid + i * 256;      // 0..1023
            const int m  = t >> 3;
            const int kq = t & 7;
            const float4 va = *reinterpret_cast<const float4*>(xr + (size_t)m * ND + k0 + kq * 4);
            uint4 ua = make_uint4(f2tf(va.x), f2tf(va.y), f2tf(va.z), f2tf(va.w));
            *reinterpret_cast<uint4*>(As + m * AB_STRIDE + kq * 4) = ua;
            const float4 vb = *reinterpret_cast<const float4*>(Wr + (size_t)m * ND + k0 + kq * 4);
            uint4 ub = make_uint4(f2tf(vb.x), f2tf(vb.y), f2tf(vb.z), f2tf(vb.w));
            *reinterpret_cast<uint4*>(Bs + m * AB_STRIDE + kq * 4) = ub;
        }
        __syncthreads();
#pragma unroll
        for (int ks = 0; ks < 4; ks++) {
            uint32_t af[4][4], bf[4][2];
            const int ar = wm * 64 + (lane >> 2);
            const int ac = ks * 8 + (lane & 3);
#pragma unroll
            for (int mf = 0; mf < 4; mf++) {
                const int r = ar + mf * 16;
                af[mf][0] = As[r * AB_STRIDE + ac];
                af[mf][1] = As[(r + 8) * AB_STRIDE + ac];
                af[mf][2] = As[r * AB_STRIDE + ac + 4];
                af[mf][3] = As[(r + 8) * AB_STRIDE + ac + 4];
            }
            const int bc = wn * 32 + (lane >> 2);
#pragma unroll
            for (int nf = 0; nf < 4; nf++) {
                const int n = bc + nf * 8;
                bf[nf][0] = Bs[n * AB_STRIDE + ac];
                bf[nf][1] = Bs[n * AB_STRIDE + ac + 4];
            }
#pragma unroll
            for (int mf = 0; mf < 4; mf++)
#pragma unroll
                for (int nf = 0; nf < 4; nf++)
                    mma_tf32(acc[mf][nf], af[mf][0], af[mf][1], af[mf][2], af[mf][3],
                             bf[nf][0], bf[nf][1]);
        }
        __syncthreads();
    }

    // q -> SMEM (tf32 bits)
    {
        const int r0 = wm * 64 + (lane >> 2);
        const int cb = wn * 32 + 2 * (lane & 3);
#pragma unroll
        for (int mf = 0; mf < 4; mf++)
#pragma unroll
            for (int nf = 0; nf < 4; nf++) {
                const int r = r0 + mf * 16;
                const int c = cb + nf * 8;
                uint2 u0; u0.x = f2tf(acc[mf][nf][0]); u0.y = f2tf(acc[mf][nf][1]);
                *reinterpret_cast<uint2*>(qs + r * QS_STRIDE + c) = u0;
                uint2 u1; u1.x = f2tf(acc[mf][nf][2]); u1.y = f2tf(acc[mf][nf][3]);
                *reinterpret_cast<uint2*>(qs + (r + 8) * QS_STRIDE + c) = u1;
            }
    }
    __syncthreads();

    // load the two per-head M matrices (overlay As/Bs)
    {
        const float* Mg = g_M + ((size_t)bt * NH + ntile * 2) * (DH * DH);
#pragma unroll
        for (int i = 0; i < 8; i++) {
            const int t  = tid + i * 256;        // 0..2047 float4s
            const int hl = t >> 10;
            const int rem = (t * 4) & 4095;
            const int dd = rem >> 6;
            const int e  = rem & 63;
            const float4 vm = *reinterpret_cast<const float4*>(Mg + (size_t)t * 4);
            uint4 um = make_uint4(f2tf(vm.x), f2tf(vm.y), f2tf(vm.z), f2tf(vm.w));
            *reinterpret_cast<uint4*>(Ms + hl * (DH * MS_STRIDE) + dd * MS_STRIDE + e) = um;
        }
    }
    __syncthreads();

    // ---------------- stage 2: q @ M ----------------
    float acc2[4][4][4];
#pragma unroll
    for (int i = 0; i < 4; i++)
#pragma unroll
        for (int j = 0; j < 4; j++)
#pragma unroll
            for (int r = 0; r < 4; r++) acc2[i][j][r] = 0.f;

    const int hl = wn >> 1;            // head within the 2-head tile
    const int e0 = (wn & 1) * 32;      // e offset within head
    const uint32_t* Mh = Ms + hl * (DH * MS_STRIDE);

#pragma unroll
    for (int ks = 0; ks < 8; ks++) {
        const int kc = ks * 8;
        uint32_t af[4][4], bf[4][2];
        const int ar = wm * 64 + (lane >> 2);
        const int ac = hl * 64 + kc + (lane & 3);
#pragma unroll
        for (int mf = 0; mf < 4; mf++) {
            const int r = ar + mf * 16;
            af[mf][0] = qs[r * QS_STRIDE + ac];
            af[mf][1] = qs[(r + 8) * QS_STRIDE + ac];
            af[mf][2] = qs[r * QS_STRIDE + ac + 4];
            af[mf][3] = qs[(r + 8) * QS_STRIDE + ac + 4];
        }
        const int brow = kc + (lane & 3);
        const int bc   = e0 + (lane >> 2);
#pragma unroll
        for (int nf = 0; nf < 4; nf++) {
            bf[nf][0] = Mh[brow * MS_STRIDE + bc + nf * 8];
            bf[nf][1] = Mh[(brow + 4) * MS_STRIDE + bc + nf * 8];
        }
#pragma unroll
        for (int mf = 0; mf < 4; mf++)
#pragma unroll
            for (int nf = 0; nf < 4; nf++)
                mma_tf32(acc2[mf][nf], af[mf][0], af[mf][1], af[mf][2], af[mf][3],
                         bf[nf][0], bf[nf][1]);
    }

    // ---------------- epilogue: out = x + a ----------------
    {
        const size_t base = (size_t)bt * NL * ND + (size_t)ntile * 128;
        const int r0 = wm * 64 + (lane >> 2);
        const int cb = wn * 32 + 2 * (lane & 3);
#pragma unroll
        for (int mf = 0; mf < 4; mf++)
#pragma unroll
            for (int nf = 0; nf < 4; nf++) {
                const int r = r0 + mf * 16;
                const int c = cb + nf * 8;
                const size_t i0 = base + (size_t)r * ND + c;
                float2 xv0 = *reinterpret_cast<const float2*>(x + i0);
                float2 o0;
                o0.x = xv0.x + acc2[mf][nf][0];
                o0.y = xv0.y + acc2[mf][nf][1];
                *reinterpret_cast<float2*>(out + i0) = o0;
                const size_t i1 = i0 + (size_t)8 * ND;
                float2 xv1 = *reinterpret_cast<const float2*>(x + i1);
                float2 o1;
                o1.x = xv1.x + acc2[mf][nf][2];
                o1.y = xv1.y + acc2[mf][nf][3];
                *reinterpret_cast<float2*>(out + i1) = o1;
            }
    }
}

// ============================================================
extern "C" void kernel_launch(void* const* d_in, const int* in_sizes, int n_in,
                              void* d_out, int out_size) {
    // metadata order: input_ids, speaker_ids, token_embeddings, edu_embeddings, Wk, Wv, Wq
    const int*   spk = (const int*)d_in[1];
    const float* tok = (const float*)d_in[2];
    const float* edu = (const float*)d_in[3];
    const float* Wk  = (const float*)d_in[4];
    const float* Wv  = (const float*)d_in[5];
    const float* Wq  = (const float*)d_in[6];
    float* out = (float*)d_out;

    kv_kernel<<<dim3(12, 4, 2), 256>>>(edu, Wk, Wv);
    m_kernel<<<dim3(8, NH, NB), 256>>>(spk);

    const int smem_bytes = SMEM_UINTS * 4;   // 104448
    cudaFuncSetAttribute(main_kernel, cudaFuncAttributeMaxDynamicSharedMemorySize, smem_bytes);
    main_kernel<<<dim3(6, NBT), 256, smem_bytes>>>(tok, Wq, out);
}

// round 3
// speedup vs baseline: 1.2409x; 1.2409x over previous
#include <cuda_runtime.h>
#include <cstdint>

#define NH  12
#define NB  4
#define NT  64
#define NL  128
#define ND  768
#define DH  64
#define NBT 256   // NB*NT

// ---------------- device scratch ----------------
__device__ float g_kp[(size_t)8 * NBT * ND];              // [kv(2)][part(4)][bt][col]
__device__ float g_M[(size_t)NBT * NH * DH * DH];         // [bt][h][d][e]

// ---------------- helpers ----------------
__device__ __forceinline__ uint32_t smem_u32(const void* p) {
    uint32_t a;
    asm("{ .reg .u64 t; cvta.to.shared.u64 t, %1; cvt.u32.u64 %0, t; }" : "=r"(a) : "l"(p));
    return a;
}
__device__ __forceinline__ uint32_t f2tf(float x) {
    uint32_t r;
    asm("cvt.rna.tf32.f32 %0, %1;" : "=r"(r) : "f"(x));
    return r;
}
__device__ __forceinline__ void cp16(uint32_t dst, const void* src) {
    asm volatile("cp.async.cg.shared.global [%0], [%1], 16;" :: "r"(dst), "l"(src) : "memory");
}
__device__ __forceinline__ void cp_commit() {
    asm volatile("cp.async.commit_group;" ::: "memory");
}
template <int N>
__device__ __forceinline__ void cp_wait() {
    asm volatile("cp.async.wait_group %0;" :: "n"(N) : "memory");
}
__device__ __forceinline__ void mma_tf32(float c[4],
                                         uint32_t a0, uint32_t a1, uint32_t a2, uint32_t a3,
                                         uint32_t b0, uint32_t b1) {
    asm volatile(
        "mma.sync.aligned.m16n8k8.row.col.f32.tf32.tf32.f32 "
        "{%0,%1,%2,%3}, {%4,%5,%6,%7}, {%8,%9}, {%0,%1,%2,%3};"
        : "+f"(c[0]), "+f"(c[1]), "+f"(c[2]), "+f"(c[3])
        : "r"(a0), "r"(a1), "r"(a2), "r"(a3), "r"(b0), "r"(b1));
}

// ============================================================
// kv: k = edu @ Wk^T, v = edu @ Wv^T; K split 4-way, partial
// outputs (deterministic, no atomics). grid (12, 4, 8), 256 thr.
// z = kvsel*4 + part
// ============================================================
__global__ void __launch_bounds__(256) kv_kernel(const float* __restrict__ edu,
                                                 const float* __restrict__ Wk,
                                                 const float* __restrict__ Wv) {
    const int z = blockIdx.z;
    const float* W = (z >> 2) ? Wv : Wk;
    float* go = g_kp + (size_t)z * NBT * ND;
    const int kbase = (z & 3) * 192;

    __shared__ float As[16][68];
    __shared__ float Bs[16][68];

    const int tid = threadIdx.x;
    const int tx = tid & 15, ty = tid >> 4;
    const int m0 = blockIdx.y * 64, n0 = blockIdx.x * 64;

    float acc[4][4];
#pragma unroll
    for (int i = 0; i < 4; i++)
#pragma unroll
        for (int j = 0; j < 4; j++) acc[i][j] = 0.f;

    const int lk = tid & 15, lr = tid >> 4;

    for (int kt = 0; kt < 12; kt++) {
        const int k0 = kbase + kt * 16;
#pragma unroll
        for (int p = 0; p < 4; p++) {
            const int r = lr + p * 16;
            As[lk][r] = edu[(size_t)(m0 + r) * ND + k0 + lk];
            Bs[lk][r] = W[(size_t)(n0 + r) * ND + k0 + lk];
        }
        __syncthreads();
#pragma unroll
        for (int k = 0; k < 16; k++) {
            float a[4], b[4];
#pragma unroll
            for (int i = 0; i < 4; i++) a[i] = As[k][ty * 4 + i];
#pragma unroll
            for (int j = 0; j < 4; j++) b[j] = Bs[k][tx * 4 + j];
#pragma unroll
            for (int i = 0; i < 4; i++)
#pragma unroll
                for (int j = 0; j < 4; j++) acc[i][j] += a[i] * b[j];
        }
        __syncthreads();
    }
#pragma unroll
    for (int i = 0; i < 4; i++)
#pragma unroll
        for (int j = 0; j < 4; j++)
            go[(size_t)(m0 + ty * 4 + i) * ND + n0 + tx * 4 + j] = acc[i][j];
}

// ============================================================
// m: speaker-segmented inclusive prefix of k (x) v -> g_M[bt][h][d][e]
// sums the 4 K-split partials while loading. grid (8, 12, 4).
// ============================================================
__global__ void __launch_bounds__(256) m_kernel(const int* __restrict__ spk) {
    const int s = blockIdx.x, h = blockIdx.y, b = blockIdx.z;
    const int tid = threadIdx.x;

    __shared__ int   sps[NT];
    __shared__ float kk[DH];
    __shared__ float vv[DH];

    if (tid < NT) sps[tid] = spk[b * NT + tid];
    __syncthreads();

    float acc[16];
#pragma unroll
    for (int r = 0; r < 16; r++) acc[r] = 0.f;

    const int dd = tid >> 2;
    const int e0 = (tid & 3) * 16;

    for (int t = 0; t < NT; t++) {
        if (sps[t] != s) continue;
        const int bt = b * NT + t;
        if (tid < DH) {
            float sum = 0.f;
#pragma unroll
            for (int p = 0; p < 4; p++)
                sum += g_kp[((size_t)p * NBT + bt) * ND + h * DH + tid];
            kk[tid] = sum;
        } else if (tid < 2 * DH) {
            float sum = 0.f;
#pragma unroll
            for (int p = 0; p < 4; p++)
                sum += g_kp[((size_t)(4 + p) * NBT + bt) * ND + h * DH + (tid - DH)];
            vv[tid - DH] = sum;
        }
        __syncthreads();

        const float kd = kk[dd];
#pragma unroll
        for (int r = 0; r < 16; r++) acc[r] += kd * vv[e0 + r];

        float4* dst = reinterpret_cast<float4*>(
            &g_M[((size_t)bt * NH + h) * (DH * DH) + tid * 16]);
        dst[0] = make_float4(acc[0], acc[1], acc[2], acc[3]);
        dst[1] = make_float4(acc[4], acc[5], acc[6], acc[7]);
        dst[2] = make_float4(acc[8], acc[9], acc[10], acc[11]);
        dst[3] = make_float4(acc[12], acc[13], acc[14], acc[15]);
        __syncthreads();
    }
}

// ============================================================
// main: fused  out = x + (x @ Wq^T) per-head@ M
// grid (6 n-tiles, 256 bt), 256 threads = 8 warps (2x4)
// Stage 1: 128x128 q-tile, K=768 in 12 chunks of 64,
//          cp.async double-buffered, cvt.rna on fragment load.
// Stage 2: per-head (128x64)@(64x64), + residual.
// ============================================================
#define KC 64
#define AB_STRIDE 68
#define BUF_UINTS (2 * NL * AB_STRIDE)      // A+B for one stage = 17408 uints
#define QS_STRIDE 132
#define MS_STRIDE 72
#define SMEM_UINTS (2 * BUF_UINTS + NL * QS_STRIDE)   // 51712 uints = 206848 B

__global__ void __launch_bounds__(256, 1) main_kernel(const float* __restrict__ x,
                                                      const float* __restrict__ Wq,
                                                      float* __restrict__ out) {
    extern __shared__ uint32_t sm[];
    const uint32_t sb = smem_u32(sm);
    uint32_t* qs = sm + 2 * BUF_UINTS;       // 128 x 132, tf32 bits
    uint32_t* Ms = sm;                        // overlay buffer 0 after stage 1

    const int tid = threadIdx.x;
    const int lane = tid & 31;
    const int wid = tid >> 5;
    const int wm = wid >> 2;    // 0..1
    const int wn = wid & 3;     // 0..3
    const int ntile = blockIdx.x;
    const int bt = blockIdx.y;

    const float* xr = x + (size_t)bt * NL * ND;
    const float* Wr = Wq + (size_t)ntile * 128 * ND;

    float acc[4][4][4];
#pragma unroll
    for (int i = 0; i < 4; i++)
#pragma unroll
        for (int j = 0; j < 4; j++)
#pragma unroll
            for (int r = 0; r < 4; r++) acc[i][j][r] = 0.f;

    // ---- stage 1: cp.async double-buffered pipeline ----
    auto stage_load = [&](int buf, int k0) {
        const uint32_t abase = sb + (uint32_t)buf * BUF_UINTS * 4;
        const uint32_t bbase = abase + NL * AB_STRIDE * 4;
#pragma unroll
        for (int i = 0; i < 8; i++) {
            const int t = tid + i * 256;      // 0..2047
            const int m = t >> 4;
            const int kq = t & 15;
            const uint32_t off = (uint32_t)(m * AB_STRIDE + kq * 4) * 4;
            cp16(abase + off, xr + (size_t)m * ND + k0 + kq * 4);
            cp16(bbase + off, Wr + (size_t)m * ND + k0 + kq * 4);
        }
    };

    stage_load(0, 0);
    cp_commit();

    for (int kt = 0; kt < 12; kt++) {
        const int cur = kt & 1;
        if (kt < 11) {
            stage_load(cur ^ 1, (kt + 1) * KC);
            cp_commit();
            cp_wait<1>();
        } else {
            cp_wait<0>();
        }
        __syncthreads();

        const uint32_t* As = sm + cur * BUF_UINTS;
        const uint32_t* Bs = As + NL * AB_STRIDE;

#pragma unroll
        for (int ks = 0; ks < 8; ks++) {
            uint32_t af[4][4], bf[4][2];
            const int ar = wm * 64 + (lane >> 2);
            const int ac = ks * 8 + (lane & 3);
#pragma unroll
            for (int mf = 0; mf < 4; mf++) {
                const int r = ar + mf * 16;
                af[mf][0] = f2tf(__uint_as_float(As[r * AB_STRIDE + ac]));
                af[mf][1] = f2tf(__uint_as_float(As[(r + 8) * AB_STRIDE + ac]));
                af[mf][2] = f2tf(__uint_as_float(As[r * AB_STRIDE + ac + 4]));
                af[mf][3] = f2tf(__uint_as_float(As[(r + 8) * AB_STRIDE + ac + 4]));
            }
            const int bc = wn * 32 + (lane >> 2);
#pragma unroll
            for (int nf = 0; nf < 4; nf++) {
                const int n = bc + nf * 8;
                bf[nf][0] = f2tf(__uint_as_float(Bs[n * AB_STRIDE + ac]));
                bf[nf][1] = f2tf(__uint_as_float(Bs[n * AB_STRIDE + ac + 4]));
            }
#pragma unroll
            for (int mf = 0; mf < 4; mf++)
#pragma unroll
                for (int nf = 0; nf < 4; nf++)
                    mma_tf32(acc[mf][nf], af[mf][0], af[mf][1], af[mf][2], af[mf][3],
                             bf[nf][0], bf[nf][1]);
        }
        __syncthreads();
    }

    // ---- q -> SMEM (tf32 bits) ----
    {
        const int r0 = wm * 64 + (lane >> 2);
        const int cb = wn * 32 + 2 * (lane & 3);
#pragma unroll
        for (int mf = 0; mf < 4; mf++)
#pragma unroll
            for (int nf = 0; nf < 4; nf++) {
                const int r = r0 + mf * 16;
                const int c = cb + nf * 8;
                uint2 u0; u0.x = f2tf(acc[mf][nf][0]); u0.y = f2tf(acc[mf][nf][1]);
                *reinterpret_cast<uint2*>(qs + r * QS_STRIDE + c) = u0;
                uint2 u1; u1.x = f2tf(acc[mf][nf][2]); u1.y = f2tf(acc[mf][nf][3]);
                *reinterpret_cast<uint2*>(qs + (r + 8) * QS_STRIDE + c) = u1;
            }
    }

    // ---- M (2 heads) -> SMEM (tf32 bits), overlaying buffer 0 ----
    {
        const float* Mg = g_M + ((size_t)bt * NH + ntile * 2) * (DH * DH);
#pragma unroll
        for (int i = 0; i < 8; i++) {
            const int t = tid + i * 256;       // float4 index, 0..2047
            const int hl = t >> 10;
            const int rem = (t * 4) & 4095;
            const int dd = rem >> 6;
            const int e = rem & 63;
            const float4 vm = *reinterpret_cast<const float4*>(Mg + (size_t)t * 4);
            uint4 um = make_uint4(f2tf(vm.x), f2tf(vm.y), f2tf(vm.z), f2tf(vm.w));
            *reinterpret_cast<uint4*>(Ms + hl * (DH * MS_STRIDE) + dd * MS_STRIDE + e) = um;
        }
    }
    __syncthreads();

    // ---- stage 2: q @ M per head ----
    float acc2[4][4][4];
#pragma unroll
    for (int i = 0; i < 4; i++)
#pragma unroll
        for (int j = 0; j < 4; j++)
#pragma unroll
            for (int r = 0; r < 4; r++) acc2[i][j][r] = 0.f;

    const int hl = wn >> 1;
    const int e0 = (wn & 1) * 32;
    const uint32_t* Mh = Ms + hl * (DH * MS_STRIDE);

#pragma unroll
    for (int ks = 0; ks < 8; ks++) {
        const int kc = ks * 8;
        uint32_t af[4][4], bf[4][2];
        const int ar = wm * 64 + (lane >> 2);
        const int ac = hl * 64 + kc + (lane & 3);
#pragma unroll
        for (int mf = 0; mf < 4; mf++) {
            const int r = ar + mf * 16;
            af[mf][0] = qs[r * QS_STRIDE + ac];
            af[mf][1] = qs[(r + 8) * QS_STRIDE + ac];
            af[mf][2] = qs[r * QS_STRIDE + ac + 4];
            af[mf][3] = qs[(r + 8) * QS_STRIDE + ac + 4];
        }
        const int brow = kc + (lane & 3);
        const int bc = e0 + (lane >> 2);
#pragma unroll
        for (int nf = 0; nf < 4; nf++) {
            bf[nf][0] = Mh[brow * MS_STRIDE + bc + nf * 8];
            bf[nf][1] = Mh[(brow + 4) * MS_STRIDE + bc + nf * 8];
        }
#pragma unroll
        for (int mf = 0; mf < 4; mf++)
#pragma unroll
            for (int nf = 0; nf < 4; nf++)
                mma_tf32(acc2[mf][nf], af[mf][0], af[mf][1], af[mf][2], af[mf][3],
                         bf[nf][0], bf[nf][1]);
    }

    // ---- epilogue: out = x + a ----
    {
        const size_t base = (size_t)bt * NL * ND + (size_t)ntile * 128;
        const int r0 = wm * 64 + (lane >> 2);
        const int cb = wn * 32 + 2 * (lane & 3);
#pragma unroll
        for (int mf = 0; mf < 4; mf++)
#pragma unroll
            for (int nf = 0; nf < 4; nf++) {
                const int r = r0 + mf * 16;
                const int c = cb + nf * 8;
                const size_t i0 = base + (size_t)r * ND + c;
                float2 xv0 = *reinterpret_cast<const float2*>(x + i0);
                float2 o0;
                o0.x = xv0.x + acc2[mf][nf][0];
                o0.y = xv0.y + acc2[mf][nf][1];
                *reinterpret_cast<float2*>(out + i0) = o0;
                const size_t i1 = i0 + (size_t)8 * ND;
                float2 xv1 = *reinterpret_cast<const float2*>(x + i1);
                float2 o1;
                o1.x = xv1.x + acc2[mf][nf][2];
                o1.y = xv1.y + acc2[mf][nf][3];
                *reinterpret_cast<float2*>(out + i1) = o1;
            }
    }
}

// ============================================================
extern "C" void kernel_launch(void* const* d_in, const int* in_sizes, int n_in,
                              void* d_out, int out_size) {
    // order: input_ids, speaker_ids, token_embeddings, edu_embeddings, Wk, Wv, Wq
    const int*   spk = (const int*)d_in[1];
    const float* tok = (const float*)d_in[2];
    const float* edu = (const float*)d_in[3];
    const float* Wk  = (const float*)d_in[4];
    const float* Wv  = (const float*)d_in[5];
    const float* Wq  = (const float*)d_in[6];
    float* out = (float*)d_out;

    kv_kernel<<<dim3(12, 4, 8), 256>>>(edu, Wk, Wv);
    m_kernel<<<dim3(8, NH, NB), 256>>>(spk);

    const int smem_bytes = SMEM_UINTS * 4;   // 206848
    cudaFuncSetAttribute(main_kernel, cudaFuncAttributeMaxDynamicSharedMemorySize, smem_bytes);
    main_kernel<<<dim3(6, NBT), 256, smem_bytes>>>(tok, Wq, out);
}